// round 4
// baseline (speedup 1.0000x reference)
#include <cuda_runtime.h>
#include <cstdint>

#define DB 64
#define DS 2048
#define DI 64
#define DH 128

typedef unsigned long long u64;

// ---------------- scratch (__device__ globals) -------------------------------
__device__ float g_wx0 [DB * DS * DH];   // x @ w0
__device__ float g_out0[DB * DS * DH];   // layer-0 outputs
__device__ float g_wx1 [DB * DS * DH];   // out0 @ w1
__device__ int   g_prog[DB * 32];        // [b*32+0]=p0  [+8]=pwx0  [+16]=pwx1

// ---------------- packed f32x2 helpers ---------------------------------------
__device__ __forceinline__ u64 ffma2(u64 a, u64 b, u64 c) {
    u64 d; asm("fma.rn.f32x2 %0, %1, %2, %3;" : "=l"(d) : "l"(a), "l"(b), "l"(c)); return d;
}
__device__ __forceinline__ u64 fadd2(u64 a, u64 b) {
    u64 d; asm("add.rn.f32x2 %0, %1, %2;" : "=l"(d) : "l"(a), "l"(b)); return d;
}
__device__ __forceinline__ u64 dup2(float x) {
    u64 d; asm("mov.b64 %0, {%1, %2};" : "=l"(d) : "f"(x), "f"(x)); return d;
}
__device__ __forceinline__ u64 pk2(float lo, float hi) {
    u64 d; asm("mov.b64 %0, {%1, %2};" : "=l"(d) : "f"(lo), "f"(hi)); return d;
}
__device__ __forceinline__ float2 unp2(u64 v) {
    float lo, hi; asm("mov.b64 {%0, %1}, %2;" : "=f"(lo), "=f"(hi) : "l"(v));
    return make_float2(lo, hi);
}

// ---------------- activations -------------------------------------------------
__device__ __forceinline__ float sigm(float x) {
    float e = __expf(fminf(-x, 30.f));
    return __fdividef(1.f, 1.f + e);
}
__device__ __forceinline__ float tanh_f(float x) {
    float xc = fminf(fmaxf(x, -15.f), 15.f);
    float e  = __expf(2.f * xc);
    return __fdividef(e - 1.f, e + 1.f);
}

// ---------------- flags --------------------------------------------------------
__device__ __forceinline__ int ld_acq(const int* p) {
    int v; asm volatile("ld.acquire.gpu.b32 %0, [%1];" : "=r"(v) : "l"(p)); return v;
}
__device__ __forceinline__ void st_rel(int* p, int v) {
    asm volatile("st.release.gpu.b32 [%0], %1;" :: "l"(p), "r"(v));
}
__device__ __forceinline__ void spin_ge(const int* p, int target) {
    while (ld_acq(p) < target) __nanosleep(40);
}

__global__ void reset_kernel() {
    int i = blockIdx.x * blockDim.x + threadIdx.x;
    if (i < DB * 32) g_prog[i] = 0;
}

// ============================================================================
// Projection tile: dst[t0..t0+15, 0:128] = SRC[t0..t0+15, 0:K] @ W
// W packed in smem: wpack[k2*64 + c] = {w[2k2][2c], w[2k2][2c+1],
//                                       w[2k2+1][2c], w[2k2+1][2c+1]}
// Warp = 2 tile rows; lane owns col-pairs l and l+32.
// ============================================================================
template<int K>
__device__ __forceinline__ void proj_tile(
    const float* __restrict__ src, int t0,
    const float4* __restrict__ wpack, float* __restrict__ stage,
    float* __restrict__ dst, int tid)
{
    for (int e = tid; e < 16 * K / 4; e += 256)
        reinterpret_cast<float4*>(stage)[e] =
            reinterpret_cast<const float4*>(src + (size_t)t0 * K)[e];
    __syncthreads();

    const int r2 = tid >> 5;
    const int l  = tid & 31;
    #pragma unroll 1
    for (int rr = 0; rr < 2; rr++) {
        const int row = 2 * r2 + rr;
        const float* srow = stage + row * K;
        u64 aA = 0, bA = 0, aB = 0, bB = 0;
        #pragma unroll 8
        for (int k2 = 0; k2 < K / 2; k2++) {
            float2 s2 = *reinterpret_cast<const float2*>(srow + 2 * k2);
            u64 d0 = dup2(s2.x), d1 = dup2(s2.y);
            float4 wa = wpack[k2 * 64 + l];
            float4 wb = wpack[k2 * 64 + l + 32];
            aA = ffma2(d0, pk2(wa.x, wa.y), aA);
            bA = ffma2(d1, pk2(wa.z, wa.w), bA);
            aB = ffma2(d0, pk2(wb.x, wb.y), aB);
            bB = ffma2(d1, pk2(wb.z, wb.w), bB);
        }
        *reinterpret_cast<u64*>(dst + (size_t)(t0 + row) * DH + 2 * l)      = fadd2(aA, bA);
        *reinterpret_cast<u64*>(dst + (size_t)(t0 + row) * DH + 64 + 2 * l) = fadd2(aB, bB);
    }
    __syncthreads();
}

// ============================================================================
// Proj role: one CTA per batch row; produces wx0 (free-running) and wx1
// (gated on producer progress p0), preferring wx1 when ready.
// ============================================================================
__device__ void proj_role(
    const float* __restrict__ xb, const float* __restrict__ out0b,
    const float* __restrict__ w0, const float* __restrict__ w1,
    float* __restrict__ wx0b, float* __restrict__ wx1b,
    const int* p0, int* pwx0, int* pwx1,
    float4* wp0, float4* wp1, float* stage, int tid)
{
    // pack weights into smem
    for (int e = tid; e < 32 * 64; e += 256) {
        int k2 = e >> 6, c = e & 63;
        const float* r0 = w0 + (size_t)(2 * k2) * DH + 2 * c;
        wp0[e] = make_float4(r0[0], r0[1], r0[DH], r0[DH + 1]);
    }
    for (int e = tid; e < 64 * 64; e += 256) {
        int k2 = e >> 6, c = e & 63;
        const float* r0 = w1 + (size_t)(2 * k2) * DH + 2 * c;
        wp1[e] = make_float4(r0[0], r0[1], r0[DH], r0[DH + 1]);
    }
    __syncthreads();

    __shared__ int sflag;
    const int NT = DS / 16;
    int n1 = 0;

    #pragma unroll 1
    for (int n0 = 0; n0 < NT; n0++) {
        // drain all ready wx1 tiles first (keeps consumer fed)
        while (n1 < NT) {
            if (tid == 0) sflag = (ld_acq(p0) >= n1 * 16 + 16) ? 1 : 0;
            __syncthreads();
            int ok = sflag;
            __syncthreads();
            if (!ok) break;
            proj_tile<DH>(out0b, n1 * 16, wp1, stage, wx1b, tid);
            if (tid == 0) { __threadfence(); st_rel(pwx1, n1 * 16 + 16); }
            n1++;
        }
        proj_tile<DI>(xb, n0 * 16, wp0, stage, wx0b, tid);
        if (tid == 0) { __threadfence(); st_rel(pwx0, n0 * 16 + 16); }
    }
    #pragma unroll 1
    while (n1 < NT) {
        if (tid == 0) spin_ge(p0, n1 * 16 + 16);
        __syncthreads();
        proj_tile<DH>(out0b, n1 * 16, wp1, stage, wx1b, tid);
        if (tid == 0) { __threadfence(); st_rel(pwx1, n1 * 16 + 16); }
        n1++;
    }
}

// ============================================================================
// Scan role: pure recurrence. 256 threads; thread = (col j = tid>>1, kh = tid&1).
// pre[j] = wx[s][j] + sum_k h[k]*u[k][j]; k-halves combined via shfl.xor(1).
// One __syncthreads per step. h halves padded 272B apart (bank-conflict-free).
// ============================================================================
__device__ void scan_role(
    float* __restrict__ hbuf,              // smem, 2*132 floats
    const float* __restrict__ umat, const float* __restrict__ wx,
    const float* __restrict__ bg, const float* __restrict__ bu,
    const float* __restrict__ zeta, const float* __restrict__ nu,
    const float* __restrict__ lambd, const float* __restrict__ gamma,
    float* __restrict__ outp, float* __restrict__ hT,
    const int* pwx, int* p0flag, int layer, int tid)
{
    const int j  = tid >> 1;
    const int kh = tid & 1;
    const int jp = j + (j >= 64 ? 4 : 0);   // padded store index

    u64 uk[32];
    #pragma unroll
    for (int i = 0; i < 32; i++) {
        int k = kh * 64 + 2 * i;
        uk[i] = pk2(umat[(size_t)k * DH + j], umat[(size_t)(k + 1) * DH + j]);
    }
    const float bgj  = bg[j], buj = bu[j];
    const float sz   = sigm(zeta[0]);
    const float sn   = sigm(nu[0]);
    const float gc   = fminf(fmaxf(gamma[0], 0.f), 1.f);
    const float cadd = (1.f - gc) * lambd[0];

    for (int e = tid; e < 2 * 132; e += 256) hbuf[e] = 0.f;

    if (tid == 0) spin_ge(pwx, 32);
    __syncthreads();

    float hold = 0.f;
    float wxA = wx[j], wxB = wx[DH + j];

    #pragma unroll 1
    for (int s = 0; s < DS; s++) {
        if ((s & 15) == 0 && s) {
            if (tid == 0) {
                int tgt = s + 32; if (tgt > DS) tgt = DS;
                spin_ge(pwx, tgt);
            }
            __syncthreads();
        }
        const float4* hp = reinterpret_cast<const float4*>(hbuf + (s & 1) * 132 + kh * 68);
        u64 a0 = 0, a1 = 0, a2 = 0, a3 = 0;
        #pragma unroll
        for (int i = 0; i < 16; i += 2) {
            float4 q0 = hp[i], q1 = hp[i + 1];
            a0 = ffma2(pk2(q0.x, q0.y), uk[2 * i],     a0);
            a1 = ffma2(pk2(q0.z, q0.w), uk[2 * i + 1], a1);
            a2 = ffma2(pk2(q1.x, q1.y), uk[2 * i + 2], a2);
            a3 = ffma2(pk2(q1.z, q1.w), uk[2 * i + 3], a3);
        }
        u64 acc = fadd2(fadd2(a0, a1), fadd2(a2, a3));
        acc = fadd2(acc, __shfl_xor_sync(0xFFFFFFFFu, acc, 1));
        float2 ap = unp2(acc);
        float pre = (ap.x + ap.y) + wxA;

        float zg = sigm(pre + bgj);
        float hh = tanh_f(pre + buj);
        float hn = zg * hold + (sz * (1.f - zg) + sn) * hh;
        float hc = __fmaf_rn(gc, hn, cadd);
        hold = hc;
        if (kh == 0) {
            hbuf[((s & 1) ^ 1) * 132 + jp] = hc;
            outp[(size_t)s * DH + j] = hc;
        }
        wxA = wxB;
        wxB = (s + 2 < DS) ? wx[(size_t)(s + 2) * DH + j] : 0.f;

        __syncthreads();
        if (layer == 0 && (s & 7) == 7 && tid == 0) {
            __threadfence();
            st_rel(p0flag, s + 1);
        }
    }
    if (kh == 0) hT[j] = hold;
}

// ============================================================================
__global__ void __launch_bounds__(256) fused_kernel(
    const float* __restrict__ x,
    const float* __restrict__ w0, const float* __restrict__ u0,
    const float* __restrict__ bg0, const float* __restrict__ bu0,
    const float* __restrict__ zeta0, const float* __restrict__ nu0,
    const float* __restrict__ lambd0, const float* __restrict__ gamma0,
    const float* __restrict__ w1, const float* __restrict__ u1,
    const float* __restrict__ bg1, const float* __restrict__ bu1,
    const float* __restrict__ zeta1, const float* __restrict__ nu1,
    const float* __restrict__ lambd1, const float* __restrict__ gamma1,
    float* __restrict__ out1, float* __restrict__ hT0, float* __restrict__ hT1)
{
    extern __shared__ __align__(16) unsigned char smraw[];
    const int tid  = threadIdx.x;
    const int role = blockIdx.x >> 6;          // 0=prod scan, 1=cons scan, 2=proj
    const int b    = blockIdx.x & 63;

    float* out0b = g_out0 + (size_t)b * DS * DH;
    float* wx0b  = g_wx0  + (size_t)b * DS * DH;
    float* wx1b  = g_wx1  + (size_t)b * DS * DH;
    int*   prog  = g_prog + b * 32;
    int*   p0    = prog;
    int*   pwx0  = prog + 8;
    int*   pwx1  = prog + 16;

    if (role == 2) {
        float4* wp0  = reinterpret_cast<float4*>(smraw);              // 32KB
        float4* wp1  = reinterpret_cast<float4*>(smraw + 32768);      // 64KB
        float*  stg  = reinterpret_cast<float*>(smraw + 32768 + 65536); // 8KB
        proj_role(x + (size_t)b * DS * DI, out0b, w0, w1,
                  wx0b, wx1b, p0, pwx0, pwx1, wp0, wp1, stg, tid);
    } else if (role == 0) {
        float* hbuf = reinterpret_cast<float*>(smraw);
        scan_role(hbuf, u0, wx0b, bg0, bu0, zeta0, nu0, lambd0, gamma0,
                  out0b, hT0 + (size_t)b * DH, pwx0, p0, 0, tid);
    } else {
        float* hbuf = reinterpret_cast<float*>(smraw);
        scan_role(hbuf, u1, wx1b, bg1, bu1, zeta1, nu1, lambd1, gamma1,
                  out1 + (size_t)b * DS * DH, hT1 + (size_t)b * DH,
                  pwx1, p0, 1, tid);
    }
}

// ============================================================================
extern "C" void kernel_launch(void* const* d_in, const int* in_sizes, int n_in,
                              void* d_out, int out_size)
{
    const float* x      = (const float*)d_in[0];
    const float* w0     = (const float*)d_in[1];
    const float* u0     = (const float*)d_in[2];
    const float* bg0    = (const float*)d_in[3];
    const float* bu0    = (const float*)d_in[4];
    const float* zeta0  = (const float*)d_in[5];
    const float* nu0    = (const float*)d_in[6];
    const float* lambd0 = (const float*)d_in[7];
    const float* gamma0 = (const float*)d_in[8];
    const float* w1     = (const float*)d_in[9];
    const float* u1     = (const float*)d_in[10];
    const float* bg1    = (const float*)d_in[11];
    const float* bu1    = (const float*)d_in[12];
    const float* zeta1  = (const float*)d_in[13];
    const float* nu1    = (const float*)d_in[14];
    const float* lambd1 = (const float*)d_in[15];
    const float* gamma1 = (const float*)d_in[16];
    (void)in_sizes; (void)n_in; (void)out_size;

    float* out = (float*)d_out;                    // out1: [B, S, H]
    float* hT0 = out + (size_t)DB * DS * DH;       // h_n[0]
    float* hT1 = hT0 + (size_t)DB * DH;            // h_n[1]

    const int smem_bytes = 32768 + 65536 + 8192;   // proj role footprint
    static int smem_set = 0;
    if (!smem_set) {
        cudaFuncSetAttribute(fused_kernel,
                             cudaFuncAttributeMaxDynamicSharedMemorySize, smem_bytes);
        smem_set = 1;
    }

    reset_kernel<<<1, 2048>>>();
    fused_kernel<<<3 * DB, 256, smem_bytes>>>(
        x, w0, u0, bg0, bu0, zeta0, nu0, lambd0, gamma0,
        w1, u1, bg1, bu1, zeta1, nu1, lambd1, gamma1,
        out, hT0, hT1);
}

// round 5
// speedup vs baseline: 1.4107x; 1.4107x over previous
#include <cuda_runtime.h>
#include <cstdint>

#define DB 64
#define DS 2048
#define DI 64
#define DH 128

typedef unsigned long long u64;

// ---------------- scratch (__device__ globals) -------------------------------
__device__ float g_wx0 [DB * DS * DH];   // x @ w0 (precomputed by gemm kernel)
__device__ float g_out0[DB * DS * DH];   // layer-0 outputs (producer scan)
__device__ float g_wx1a[DB * DS * 64];   // out0 @ w1[:,0:64] (producer helpers)
__device__ int   g_prog[DB * 32];        // [b*32] = p0

// ---------------- packed f32x2 helpers ---------------------------------------
__device__ __forceinline__ u64 ffma2(u64 a, u64 b, u64 c) {
    u64 d; asm("fma.rn.f32x2 %0, %1, %2, %3;" : "=l"(d) : "l"(a), "l"(b), "l"(c)); return d;
}
__device__ __forceinline__ u64 fadd2(u64 a, u64 b) {
    u64 d; asm("add.rn.f32x2 %0, %1, %2;" : "=l"(d) : "l"(a), "l"(b)); return d;
}
__device__ __forceinline__ u64 dup2(float x) {
    u64 d; asm("mov.b64 %0, {%1, %2};" : "=l"(d) : "f"(x), "f"(x)); return d;
}
__device__ __forceinline__ u64 pk2(float lo, float hi) {
    u64 d; asm("mov.b64 %0, {%1, %2};" : "=l"(d) : "f"(lo), "f"(hi)); return d;
}
__device__ __forceinline__ float2 unp2(u64 v) {
    float lo, hi; asm("mov.b64 {%0, %1}, %2;" : "=f"(lo), "=f"(hi) : "l"(v));
    return make_float2(lo, hi);
}

// ---------------- activations -------------------------------------------------
__device__ __forceinline__ float sigm(float x) {
    float e = __expf(fminf(-x, 30.f));
    return __fdividef(1.f, 1.f + e);
}
__device__ __forceinline__ float tanh_f(float x) {
    float xc = fminf(fmaxf(x, -15.f), 15.f);
    float e  = __expf(2.f * xc);
    return __fdividef(e - 1.f, e + 1.f);
}

// ---------------- flags --------------------------------------------------------
__device__ __forceinline__ int ld_acq(const int* p) {
    int v; asm volatile("ld.acquire.gpu.b32 %0, [%1];" : "=r"(v) : "l"(p)); return v;
}
__device__ __forceinline__ void st_rel(int* p, int v) {
    asm volatile("st.release.gpu.b32 [%0], %1;" :: "l"(p), "r"(v));
}
__device__ __forceinline__ void spin_ge(const int* p, int target) {
    while (ld_acq(p) < target) __nanosleep(40);
}

__global__ void reset_kernel() {
    int i = blockIdx.x * blockDim.x + threadIdx.x;
    if (i < DB * 32) g_prog[i] = 0;
}

// ============================================================================
// GEMM: OUT[row, 0:128] = X[row, 0:K] @ W[K, 128]. One row per thread.
// (R1 kernel, verified ~70us for K=64 over 131072 rows.)
// ============================================================================
template<int K>
__global__ void __launch_bounds__(256, 1) gemm_rows(
    const float* __restrict__ X, const float* __restrict__ W, float* __restrict__ OUT)
{
    extern __shared__ float ws[];
    for (int i = threadIdx.x; i < K * DH / 4; i += 256)
        reinterpret_cast<float4*>(ws)[i] = reinterpret_cast<const float4*>(W)[i];
    __syncthreads();

    int row = blockIdx.x * 256 + threadIdx.x;
    const float* xr = X + (size_t)row * K;
    float xv[K];
    #pragma unroll
    for (int i = 0; i < K / 4; i++) {
        float4 v = reinterpret_cast<const float4*>(xr)[i];
        xv[4*i] = v.x; xv[4*i+1] = v.y; xv[4*i+2] = v.z; xv[4*i+3] = v.w;
    }
    const u64* wsu = reinterpret_cast<const u64*>(ws);
    float* outr = OUT + (size_t)row * DH;

    #pragma unroll 1
    for (int cb = 0; cb < 16; cb++) {
        u64 a0 = 0, a1 = 0, a2 = 0, a3 = 0;
        #pragma unroll 16
        for (int k = 0; k < K; k++) {
            u64 xd = dup2(xv[k]);
            const u64* wr = wsu + k * (DH / 2) + cb * 4;
            a0 = ffma2(xd, wr[0], a0);
            a1 = ffma2(xd, wr[1], a1);
            a2 = ffma2(xd, wr[2], a2);
            a3 = ffma2(xd, wr[3], a3);
        }
        float2 r0 = unp2(a0), r1 = unp2(a1), r2 = unp2(a2), r3 = unp2(a3);
        reinterpret_cast<float4*>(outr)[cb*2]     = make_float4(r0.x, r0.y, r1.x, r1.y);
        reinterpret_cast<float4*>(outr)[cb*2 + 1] = make_float4(r2.x, r2.y, r3.x, r3.y);
    }
}

// ---------------- shared matvec fragment: 32 k-pairs vs 32 reg-weights --------
// src points at 64 contiguous floats (the kh-half); uw = 32 packed u64 weights.
__device__ __forceinline__ u64 matvec32(const float* src, const u64* uw) {
    const ulonglong2* hp = reinterpret_cast<const ulonglong2*>(src);
    u64 a0 = 0, a1 = 0, a2 = 0, a3 = 0;
    #pragma unroll
    for (int t = 0; t < 8; t++) {
        ulonglong2 qa = hp[2*t], qb = hp[2*t + 1];
        a0 = ffma2(qa.x, uw[4*t],     a0);
        a1 = ffma2(qa.y, uw[4*t + 1], a1);
        a2 = ffma2(qb.x, uw[4*t + 2], a2);
        a3 = ffma2(qb.y, uw[4*t + 3], a3);
    }
    return fadd2(fadd2(a0, a1), fadd2(a2, a3));
}

// combine the two kh partials (adjacent lanes) into a scalar
__device__ __forceinline__ float combine2(u64 acc) {
    acc = fadd2(acc, __shfl_xor_sync(0xFFFFFFFFu, acc, 1));
    float2 ap = unp2(acc);
    return ap.x + ap.y;
}

// ============================================================================
// Pipeline kernel: 128 CTAs x 384 threads.
//   role 0 (blocks 0..63):   producer — layer-0 scan + wx1a helpers
//   role 1 (blocks 64..127): consumer — layer-1 scan + wx1b helpers
// ============================================================================
__global__ void __launch_bounds__(384, 1) pipe_kernel(
    const float* __restrict__ u0, const float* __restrict__ u1,
    const float* __restrict__ w1,
    const float* __restrict__ bg0, const float* __restrict__ bu0,
    const float* __restrict__ zeta0, const float* __restrict__ nu0,
    const float* __restrict__ lambd0, const float* __restrict__ gamma0,
    const float* __restrict__ bg1, const float* __restrict__ bu1,
    const float* __restrict__ zeta1, const float* __restrict__ nu1,
    const float* __restrict__ lambd1, const float* __restrict__ gamma1,
    float* __restrict__ out1, float* __restrict__ hT0, float* __restrict__ hT1)
{
    __shared__ __align__(16) float hbuf[2][DH];
    __shared__ __align__(16) float ring[4][DH];     // consumer: staged out0
    __shared__ __align__(16) float wxbring[4][64];  // consumer: wx1b ring

    const int tid  = threadIdx.x;
    const int role = blockIdx.x >> 6;
    const int b    = blockIdx.x & 63;

    float*       out0b = g_out0 + (size_t)b * DS * DH;
    const float* wx0b  = g_wx0  + (size_t)b * DS * DH;
    float*       wx1ab = g_wx1a + (size_t)b * DS * 64;
    int*         p0    = g_prog + b * 32;

    if (role == 0) {
        // =========================== PRODUCER ===============================
        if (tid < 256) {
            // ---- scan warps ----
            const int j  = tid >> 1;
            const int kh = tid & 1;
            u64 uk[32];
            #pragma unroll
            for (int i = 0; i < 32; i++) {
                int k = kh * 64 + 2 * i;
                uk[i] = pk2(u0[(size_t)k * DH + j], u0[(size_t)(k + 1) * DH + j]);
            }
            const float bgj  = bg0[j], buj = bu0[j];
            const float sz   = sigm(zeta0[0]);
            const float sn   = sigm(nu0[0]);
            const float gc   = fminf(fmaxf(gamma0[0], 0.f), 1.f);
            const float cadd = (1.f - gc) * lambd0[0];

            if (tid < DH) { hbuf[0][tid] = 0.f; hbuf[1][tid] = 0.f; }
            float hold = 0.f, wxA = 0.f, wxB = 0.f;
            if (kh == 0) { wxA = wx0b[j]; wxB = wx0b[DH + j]; }
            __syncthreads();

            #pragma unroll 1
            for (int s = 0; s < DS; s++) {
                u64 acc = matvec32(&hbuf[s & 1][kh * 64], uk);
                float pre = combine2(acc);
                if (kh == 0) {
                    pre += wxA;
                    float zg = sigm(pre + bgj);
                    float hh = tanh_f(pre + buj);
                    float hn = zg * hold + (sz * (1.f - zg) + sn) * hh;
                    float hc = __fmaf_rn(gc, hn, cadd);
                    hold = hc;
                    hbuf[(s & 1) ^ 1][j] = hc;
                    out0b[(size_t)s * DH + j] = hc;
                    wxA = wxB;
                    wxB = (s + 2 < DS) ? wx0b[(size_t)(s + 2) * DH + j] : 0.f;
                }
                __syncthreads();
                if ((s & 7) == 7 && tid == 0) st_rel(p0, s);   // out0<=s, wx1a<=s-1
            }
            if (kh == 0) hT0[(size_t)b * DH + j] = hold;
            __syncthreads();
            if (tid == 0) st_rel(p0, 4096);
        } else {
            // ---- helper warps: wx1a[s-1] = h_s @ w1[:,0:64] ----
            const int htid = tid - 256;
            const int jj   = htid >> 1;     // col 0..63
            const int kh   = htid & 1;
            u64 uw[32];
            #pragma unroll
            for (int i = 0; i < 32; i++) {
                int k = kh * 64 + 2 * i;
                uw[i] = pk2(w1[(size_t)k * DH + jj], w1[(size_t)(k + 1) * DH + jj]);
            }
            __syncthreads();
            #pragma unroll 1
            for (int s = 0; s < DS; s++) {
                u64 acc = matvec32(&hbuf[s & 1][kh * 64], uw);
                float v = combine2(acc);
                if (kh == 0 && s > 0) wx1ab[(size_t)(s - 1) * 64 + jj] = v;
                __syncthreads();
            }
            // epilogue: wx1a[DS-1] from h_DS (buffer 0, DS even)
            {
                u64 acc = matvec32(&hbuf[0][kh * 64], uw);
                float v = combine2(acc);
                if (kh == 0) wx1ab[(size_t)(DS - 1) * 64 + jj] = v;
            }
            __syncthreads();
        }
    } else {
        // =========================== CONSUMER ===============================
        if (tid < 256) {
            // ---- scan warps ----
            const int j  = tid >> 1;
            const int kh = tid & 1;
            u64 uk[32];
            #pragma unroll
            for (int i = 0; i < 32; i++) {
                int k = kh * 64 + 2 * i;
                uk[i] = pk2(u1[(size_t)k * DH + j], u1[(size_t)(k + 1) * DH + j]);
            }
            const float bgj  = bg1[j], buj = bu1[j];
            const float sz   = sigm(zeta1[0]);
            const float sn   = sigm(nu1[0]);
            const float gc   = fminf(fmaxf(gamma1[0], 0.f), 1.f);
            const float cadd = (1.f - gc) * lambd1[0];

            if (tid < DH) { hbuf[0][tid] = 0.f; hbuf[1][tid] = 0.f; }
            if (tid == 0) spin_ge(p0, 16);
            __syncthreads();                       // syncA

            float hold = 0.f, wxA = 0.f, wxB = 0.f;
            if (kh == 0 && j < 64) { wxA = wx1ab[j]; wxB = wx1ab[64 + j]; }
            __syncthreads();                       // syncB1
            __syncthreads();                       // syncB2

            float* outb = out1 + (size_t)b * DS * DH;
            #pragma unroll 1
            for (int s = 0; s < DS; s++) {
                if ((s & 7) == 0 && s) {
                    if (tid == 0) spin_ge(p0, s + 12);
                    __syncthreads();
                }
                u64 acc = matvec32(&hbuf[s & 1][kh * 64], uk);
                float pre = combine2(acc);
                if (kh == 0) {
                    pre += (j < 64) ? wxA : wxbring[s & 3][j - 64];
                    float zg = sigm(pre + bgj);
                    float hh = tanh_f(pre + buj);
                    float hn = zg * hold + (sz * (1.f - zg) + sn) * hh;
                    float hc = __fmaf_rn(gc, hn, cadd);
                    hold = hc;
                    hbuf[(s & 1) ^ 1][j] = hc;
                    outb[(size_t)s * DH + j] = hc;
                    if (j < 64) {
                        wxA = wxB;
                        wxB = (s + 2 < DS) ? wx1ab[(size_t)(s + 2) * 64 + j] : 0.f;
                    }
                }
                __syncthreads();
            }
            if (kh == 0) hT1[(size_t)b * DH + j] = hold;
        } else {
            // ---- helper warps: wx1b[s+1] = out0[s+1] @ w1[:,64:128] ----
            const int htid = tid - 256;
            const int jj   = htid >> 1;     // 0..63 -> col 64+jj
            const int kh   = htid & 1;
            u64 uw[32];
            #pragma unroll
            for (int i = 0; i < 32; i++) {
                int k = kh * 64 + 2 * i;
                uw[i] = pk2(w1[(size_t)k * DH + 64 + jj],
                            w1[(size_t)(k + 1) * DH + 64 + jj]);
            }
            __syncthreads();                       // syncA
            // bootstrap: stage out0[0..2] into ring
            if (htid < 32) {
                #pragma unroll
                for (int slot = 0; slot < 3; slot++) {
                    float4 v = reinterpret_cast<const float4*>(out0b + (size_t)slot * DH)[htid];
                    reinterpret_cast<float4*>(ring[slot])[htid] = v;
                }
            }
            __syncthreads();                       // syncB1
            {   // wx1b[0] from ring[0]
                u64 acc = matvec32(&ring[0][kh * 64], uw);
                float v = combine2(acc);
                if (kh == 0) wxbring[0][jj] = v;
            }
            float4 gA = make_float4(0.f, 0.f, 0.f, 0.f);
            if (htid < 32)
                gA = reinterpret_cast<const float4*>(out0b + (size_t)3 * DH)[htid];
            __syncthreads();                       // syncB2

            #pragma unroll 1
            for (int s = 0; s < DS; s++) {
                if ((s & 7) == 0 && s) {
                    __syncthreads();               // matches scan's spin sync
                }
                if (htid < 32) {
                    reinterpret_cast<float4*>(ring[(s + 3) & 3])[htid] = gA;
                    gA = (s + 4 < DS)
                       ? reinterpret_cast<const float4*>(out0b + (size_t)(s + 4) * DH)[htid]
                       : make_float4(0.f, 0.f, 0.f, 0.f);
                }
                if (s + 1 < DS) {
                    u64 acc = matvec32(&ring[(s + 1) & 3][kh * 64], uw);
                    float v = combine2(acc);
                    if (kh == 0) wxbring[(s + 1) & 3][jj] = v;
                }
                __syncthreads();
            }
        }
    }
}

// ============================================================================
extern "C" void kernel_launch(void* const* d_in, const int* in_sizes, int n_in,
                              void* d_out, int out_size)
{
    const float* x      = (const float*)d_in[0];
    const float* w0     = (const float*)d_in[1];
    const float* u0     = (const float*)d_in[2];
    const float* bg0    = (const float*)d_in[3];
    const float* bu0    = (const float*)d_in[4];
    const float* zeta0  = (const float*)d_in[5];
    const float* nu0    = (const float*)d_in[6];
    const float* lambd0 = (const float*)d_in[7];
    const float* gamma0 = (const float*)d_in[8];
    const float* w1     = (const float*)d_in[9];
    const float* u1     = (const float*)d_in[10];
    const float* bg1    = (const float*)d_in[11];
    const float* bu1    = (const float*)d_in[12];
    const float* zeta1  = (const float*)d_in[13];
    const float* nu1    = (const float*)d_in[14];
    const float* lambd1 = (const float*)d_in[15];
    const float* gamma1 = (const float*)d_in[16];
    (void)in_sizes; (void)n_in; (void)out_size;

    float* out = (float*)d_out;                    // out1: [B, S, H]
    float* hT0 = out + (size_t)DB * DS * DH;       // h_n[0]
    float* hT1 = hT0 + (size_t)DB * DH;            // h_n[1]

    void* p;
    cudaGetSymbolAddress(&p, g_wx0);
    float* wx0p = (float*)p;

    reset_kernel<<<2, 1024>>>();
    gemm_rows<DI><<<(DB * DS) / 256, 256, DI * DH * 4>>>(x, w0, wx0p);
    pipe_kernel<<<2 * DB, 384>>>(
        u0, u1, w1,
        bg0, bu0, zeta0, nu0, lambd0, gamma0,
        bg1, bu1, zeta1, nu1, lambd1, gamma1,
        out, hT0, hT1);
}

// round 6
// speedup vs baseline: 1.5099x; 1.0703x over previous
#include <cuda_runtime.h>
#include <cstdint>

#define DB 64
#define DS 2048
#define DI 64
#define DH 128

typedef unsigned long long u64;

// ---------------- scratch (__device__ globals) -------------------------------
__device__ float g_wx0 [DB * DS * DH];   // x @ w0 (precomputed)
__device__ float g_out0[DB * DS * DH];   // layer-0 outputs
__device__ float g_wx1a[DB * DS * 64];   // out0 @ w1[:,0:64] (producer helpers)
__device__ int   g_prog[DB * 32];        // [b*32+0]=p0  [b*32+8]=pwx1a

// ---------------- packed f32x2 helpers ---------------------------------------
__device__ __forceinline__ u64 ffma2(u64 a, u64 b, u64 c) {
    u64 d; asm("fma.rn.f32x2 %0, %1, %2, %3;" : "=l"(d) : "l"(a), "l"(b), "l"(c)); return d;
}
__device__ __forceinline__ u64 fadd2(u64 a, u64 b) {
    u64 d; asm("add.rn.f32x2 %0, %1, %2;" : "=l"(d) : "l"(a), "l"(b)); return d;
}
__device__ __forceinline__ u64 dup2(float x) {
    u64 d; asm("mov.b64 %0, {%1, %2};" : "=l"(d) : "f"(x), "f"(x)); return d;
}
__device__ __forceinline__ u64 pk2(float lo, float hi) {
    u64 d; asm("mov.b64 %0, {%1, %2};" : "=l"(d) : "f"(lo), "f"(hi)); return d;
}
__device__ __forceinline__ float2 unp2(u64 v) {
    float lo, hi; asm("mov.b64 {%0, %1}, %2;" : "=f"(lo), "=f"(hi) : "l"(v));
    return make_float2(lo, hi);
}

// ---------------- fast gates ---------------------------------------------------
// sigm(x) = 1/(1 + 2^(-x*log2e)); overflow saturates to 0/1 correctly, no NaN.
__device__ __forceinline__ float sigm_fast(float x) {
    float t, r;
    asm("ex2.approx.f32 %0, %1;" : "=f"(t) : "f"(-1.4426950408889634f * x));
    asm("rcp.approx.f32 %0, %1;" : "=f"(r) : "f"(1.0f + t));
    return r;
}
// tanh(x) = 2*sigm(2x) - 1
__device__ __forceinline__ float tanh_fast(float x) {
    float t, r;
    asm("ex2.approx.f32 %0, %1;" : "=f"(t) : "f"(-2.8853900817779268f * x));
    asm("rcp.approx.f32 %0, %1;" : "=f"(r) : "f"(1.0f + t));
    return __fmaf_rn(2.0f, r, -1.0f);
}

// ---------------- global flags -------------------------------------------------
__device__ __forceinline__ int ld_acq(const int* p) {
    int v; asm volatile("ld.acquire.gpu.b32 %0, [%1];" : "=r"(v) : "l"(p)); return v;
}
__device__ __forceinline__ void st_rel(int* p, int v) {
    asm volatile("st.release.gpu.b32 [%0], %1;" :: "l"(p), "r"(v));
}
__device__ __forceinline__ void spin_ge(const int* p, int target) {
    while (ld_acq(p) < target) __nanosleep(40);
}

// ---------------- smem flags (cta scope) ---------------------------------------
__device__ __forceinline__ unsigned smaddr(const void* p) {
    unsigned a;
    asm("{ .reg .u64 t; cvta.to.shared.u64 t, %1; cvt.u32.u64 %0, t; }"
        : "=r"(a) : "l"(p));
    return a;
}
__device__ __forceinline__ int ld_acq_sh(unsigned a) {
    int v; asm volatile("ld.acquire.cta.shared.b32 %0, [%1];" : "=r"(v) : "r"(a)); return v;
}
__device__ __forceinline__ void st_rel_sh(unsigned a, int v) {
    asm volatile("st.release.cta.shared.b32 [%0], %1;" :: "r"(a), "r"(v));
}
__device__ __forceinline__ void spin_sh(unsigned a, int tgt) {
    while (ld_acq_sh(a) < tgt) __nanosleep(20);
}

#define BAR_SCAN()   asm volatile("bar.sync 1, 128;" ::: "memory")
#define BAR_HELP()   asm volatile("bar.sync 2, 64;"  ::: "memory")

__global__ void reset_kernel() {
    int i = blockIdx.x * blockDim.x + threadIdx.x;
    if (i < DB * 32) g_prog[i] = 0;
}

// ============================================================================
// GEMM: OUT[row, 0:128] = X[row, 0:K] @ W[K,128]. One row per thread. (~70us)
// ============================================================================
template<int K>
__global__ void __launch_bounds__(256, 1) gemm_rows(
    const float* __restrict__ X, const float* __restrict__ W, float* __restrict__ OUT)
{
    extern __shared__ float ws[];
    for (int i = threadIdx.x; i < K * DH / 4; i += 256)
        reinterpret_cast<float4*>(ws)[i] = reinterpret_cast<const float4*>(W)[i];
    __syncthreads();

    int row = blockIdx.x * 256 + threadIdx.x;
    const float* xr = X + (size_t)row * K;
    float xv[K];
    #pragma unroll
    for (int i = 0; i < K / 4; i++) {
        float4 v = reinterpret_cast<const float4*>(xr)[i];
        xv[4*i] = v.x; xv[4*i+1] = v.y; xv[4*i+2] = v.z; xv[4*i+3] = v.w;
    }
    const u64* wsu = reinterpret_cast<const u64*>(ws);
    float* outr = OUT + (size_t)row * DH;

    #pragma unroll 1
    for (int cb = 0; cb < 16; cb++) {
        u64 a0 = 0, a1 = 0, a2 = 0, a3 = 0;
        #pragma unroll 16
        for (int k = 0; k < K; k++) {
            u64 xd = dup2(xv[k]);
            const u64* wr = wsu + k * (DH / 2) + cb * 4;
            a0 = ffma2(xd, wr[0], a0);
            a1 = ffma2(xd, wr[1], a1);
            a2 = ffma2(xd, wr[2], a2);
            a3 = ffma2(xd, wr[3], a3);
        }
        float2 r0 = unp2(a0), r1 = unp2(a1), r2 = unp2(a2), r3 = unp2(a3);
        reinterpret_cast<float4*>(outr)[cb*2]     = make_float4(r0.x, r0.y, r1.x, r1.y);
        reinterpret_cast<float4*>(outr)[cb*2 + 1] = make_float4(r2.x, r2.y, r3.x, r3.y);
    }
}

// ---------------- full-k matvec: 128 floats (broadcast smem) vs 64 u64 regs ---
__device__ __forceinline__ float mv128(const float* row, const u64* w) {
    const ulonglong2* hp = reinterpret_cast<const ulonglong2*>(row);
    u64 a0 = 0, a1 = 0, a2 = 0, a3 = 0, a4 = 0, a5 = 0, a6 = 0, a7 = 0;
    #pragma unroll
    for (int t = 0; t < 32; t += 4) {
        ulonglong2 q0 = hp[t], q1 = hp[t+1], q2 = hp[t+2], q3 = hp[t+3];
        a0 = ffma2(q0.x, w[2*t + 0], a0);  a1 = ffma2(q0.y, w[2*t + 1], a1);
        a2 = ffma2(q1.x, w[2*t + 2], a2);  a3 = ffma2(q1.y, w[2*t + 3], a3);
        a4 = ffma2(q2.x, w[2*t + 4], a4);  a5 = ffma2(q2.y, w[2*t + 5], a5);
        a6 = ffma2(q3.x, w[2*t + 6], a6);  a7 = ffma2(q3.y, w[2*t + 7], a7);
    }
    u64 s = fadd2(fadd2(fadd2(a0, a1), fadd2(a2, a3)),
                  fadd2(fadd2(a4, a5), fadd2(a6, a7)));
    float2 p = unp2(s);
    return p.x + p.y;
}

// ---------------- shared-memory block ------------------------------------------
struct SM {
    float hring[16][DH];     // 8KB : h state entering step t lives at [t & 15]
    float wxb[16][64];       // 4KB : consumer: wx1b ring
    float stage[2][8][DH];   // 8KB : consumer helper staging of out0 blocks
    int sc;                  // scan steps completed (producer/consumer local)
    int hc;                  // producer helper progress (wx1a rows done)
    int hcb;                 // consumer helper progress (wx1b rows done)
    int sc1;                 // consumer scan progress (for wxb ring safety)
};

// ============================================================================
__global__ void __launch_bounds__(192, 1) pipe_kernel(
    const float* __restrict__ u0, const float* __restrict__ u1,
    const float* __restrict__ w1,
    const float* __restrict__ bg0, const float* __restrict__ bu0,
    const float* __restrict__ zeta0, const float* __restrict__ nu0,
    const float* __restrict__ lambd0, const float* __restrict__ gamma0,
    const float* __restrict__ bg1, const float* __restrict__ bu1,
    const float* __restrict__ zeta1, const float* __restrict__ nu1,
    const float* __restrict__ lambd1, const float* __restrict__ gamma1,
    float* __restrict__ out1, float* __restrict__ hT0, float* __restrict__ hT1)
{
    __shared__ __align__(16) SM sm;

    const int tid  = threadIdx.x;
    const int role = blockIdx.x >> 6;   // 0 = producer, 1 = consumer
    const int b    = blockIdx.x & 63;

    float*       out0b  = g_out0 + (size_t)b * DS * DH;
    const float* wx0b   = g_wx0  + (size_t)b * DS * DH;
    float*       wx1ab  = g_wx1a + (size_t)b * DS * 64;
    int*         p0     = g_prog + b * 32;
    int*         pwx1a  = g_prog + b * 32 + 8;

    const unsigned a_sc  = smaddr(&sm.sc);
    const unsigned a_hc  = smaddr(&sm.hc);
    const unsigned a_hcb = smaddr(&sm.hcb);
    const unsigned a_sc1 = smaddr(&sm.sc1);

    if (tid == 0) { sm.sc = 0; sm.hc = 0; sm.hcb = 0; sm.sc1 = 0; }
    if (tid < DH) sm.hring[0][tid] = 0.f;
    __syncthreads();

    if (role == 0) {
        // ============================ PRODUCER ==============================
        if (tid < DH) {
            // ---- scan warps (0-3): pure layer-0 recurrence ----
            const int j = tid;
            u64 uk[64];
            #pragma unroll
            for (int i = 0; i < 64; i++)
                uk[i] = pk2(u0[(size_t)(2*i) * DH + j], u0[(size_t)(2*i+1) * DH + j]);
            const float bgj  = bg0[j], buj = bu0[j];
            const float sz   = sigm_fast(zeta0[0]);
            const float sn   = sigm_fast(nu0[0]);
            const float gc   = fminf(fmaxf(gamma0[0], 0.f), 1.f);
            const float cadd = (1.f - gc) * lambd0[0];

            float hold = 0.f;
            float wxA = wx0b[j], wxB = wx0b[DH + j];

            #pragma unroll 1
            for (int s = 0; s < DS; s++) {
                if ((s & 7) == 0 && s >= 16)       // h-ring safety vs helpers
                    spin_sh(a_hc, s - 8);
                float pre = mv128(sm.hring[s & 15], uk) + wxA;
                float zg  = sigm_fast(pre + bgj);
                float th  = tanh_fast(pre + buj);
                float hn  = zg * hold + (sz * (1.f - zg) + sn) * th;
                float hcv = __fmaf_rn(gc, hn, cadd);
                hold = hcv;
                sm.hring[(s + 1) & 15][j] = hcv;
                out0b[(size_t)s * DH + j] = hcv;
                wxA = wxB;
                wxB = (s + 2 < DS) ? wx0b[(size_t)(s + 2) * DH + j] : 0.f;
                BAR_SCAN();
                if (tid == 0) {
                    st_rel_sh(a_sc, s + 1);
                    if ((s & 7) == 7) st_rel(p0, s + 1);
                }
            }
            if (tid < DH) hT0[(size_t)b * DH + tid] = hold;
        } else {
            // ---- helper warps (4-5): wx1a[s] = out0[s] @ w1[:,0:64] ----
            const int ht = tid - 128;               // 0..63 = output col
            u64 uw[64];
            #pragma unroll
            for (int i = 0; i < 64; i++)
                uw[i] = pk2(w1[(size_t)(2*i) * DH + ht], w1[(size_t)(2*i+1) * DH + ht]);

            #pragma unroll 1
            for (int s = 0; s < DS; s++) {
                spin_sh(a_sc, s + 1);               // out0[s] = hring[(s+1)&15]
                float v = mv128(sm.hring[(s + 1) & 15], uw);
                wx1ab[(size_t)s * 64 + ht] = v;
                if ((s & 7) == 7) {
                    BAR_HELP();
                    if (ht == 0) { st_rel(pwx1a, s + 1); st_rel_sh(a_hc, s + 1); }
                }
            }
        }
    } else {
        // ============================ CONSUMER ==============================
        if (tid < DH) {
            // ---- scan warps (0-3): layer-1 recurrence ----
            const int j = tid;
            u64 uk[64];
            #pragma unroll
            for (int i = 0; i < 64; i++)
                uk[i] = pk2(u1[(size_t)(2*i) * DH + j], u1[(size_t)(2*i+1) * DH + j]);
            const float bgj  = bg1[j], buj = bu1[j];
            const float sz   = sigm_fast(zeta1[0]);
            const float sn   = sigm_fast(nu1[0]);
            const float gc   = fminf(fmaxf(gamma1[0], 0.f), 1.f);
            const float cadd = (1.f - gc) * lambd1[0];

            if (tid == 0) { spin_ge(pwx1a, 16); spin_sh(a_hcb, 8); }
            BAR_SCAN();

            float hold = 0.f;
            float wxA = (j < 64) ? wx1ab[j] : 0.f;
            float wxB = (j < 64) ? wx1ab[64 + j] : 0.f;
            float* outb = out1 + (size_t)b * DS * DH;

            #pragma unroll 1
            for (int s = 0; s < DS; s++) {
                if ((s & 7) == 0 && s) {
                    if (tid == 0) {
                        int t1 = s + 16; if (t1 > DS) t1 = DS;
                        int t2 = s + 8;  if (t2 > DS) t2 = DS;
                        spin_ge(pwx1a, t1);
                        spin_sh(a_hcb, t2);
                    }
                    BAR_SCAN();
                }
                float wx = (j < 64) ? wxA : sm.wxb[s & 15][j - 64];
                float pre = mv128(sm.hring[s & 15], uk) + wx;
                float zg  = sigm_fast(pre + bgj);
                float th  = tanh_fast(pre + buj);
                float hn  = zg * hold + (sz * (1.f - zg) + sn) * th;
                float hcv = __fmaf_rn(gc, hn, cadd);
                hold = hcv;
                sm.hring[(s + 1) & 15][j] = hcv;
                outb[(size_t)s * DH + j] = hcv;
                if (j < 64) {
                    wxA = wxB;
                    wxB = (s + 2 < DS) ? wx1ab[(size_t)(s + 2) * 64 + j] : 0.f;
                }
                BAR_SCAN();
                if (tid == 0 && (s & 7) == 7) st_rel_sh(a_sc1, s + 1);
            }
            if (tid < DH) hT1[(size_t)b * DH + tid] = hold;
        } else {
            // ---- helper warps (4-5): wx1b[t] = out0[t] @ w1[:,64:128] ----
            const int ht = tid - 128;               // 0..63 -> col 64+ht
            u64 uw[64];
            #pragma unroll
            for (int i = 0; i < 64; i++)
                uw[i] = pk2(w1[(size_t)(2*i) * DH + 64 + ht],
                            w1[(size_t)(2*i+1) * DH + 64 + ht]);

            // stage block 0
            if (ht == 0) spin_ge(p0, 8);
            BAR_HELP();
            #pragma unroll
            for (int i = 0; i < 4; i++)
                reinterpret_cast<float4*>(&sm.stage[0][0][0])[ht + 64*i] =
                    reinterpret_cast<const float4*>(out0b)[ht + 64*i];
            BAR_HELP();

            #pragma unroll 1
            for (int n = 0; n < DS / 8; n++) {
                // ring safety: scan must be past rows overwritten in wxb
                if (n >= 2) spin_sh(a_sc1, 8*n - 8);
                // stage next block while computing this one
                if (n + 1 < DS / 8) {
                    if (ht == 0) spin_ge(p0, 8*(n + 1) + 8);
                    BAR_HELP();
                    const float4* src =
                        reinterpret_cast<const float4*>(out0b + (size_t)8*(n+1) * DH);
                    float4* dst = reinterpret_cast<float4*>(&sm.stage[(n+1) & 1][0][0]);
                    #pragma unroll
                    for (int i = 0; i < 4; i++) dst[ht + 64*i] = src[ht + 64*i];
                }
                #pragma unroll 1
                for (int r = 0; r < 8; r++) {
                    int t = 8*n + r;
                    float v = mv128(sm.stage[n & 1][r], uw);
                    sm.wxb[t & 15][ht] = v;
                }
                BAR_HELP();
                if (ht == 0) st_rel_sh(a_hcb, 8*n + 8);
            }
        }
    }
}

// ============================================================================
extern "C" void kernel_launch(void* const* d_in, const int* in_sizes, int n_in,
                              void* d_out, int out_size)
{
    const float* x      = (const float*)d_in[0];
    const float* w0     = (const float*)d_in[1];
    const float* u0     = (const float*)d_in[2];
    const float* bg0    = (const float*)d_in[3];
    const float* bu0    = (const float*)d_in[4];
    const float* zeta0  = (const float*)d_in[5];
    const float* nu0    = (const float*)d_in[6];
    const float* lambd0 = (const float*)d_in[7];
    const float* gamma0 = (const float*)d_in[8];
    const float* w1     = (const float*)d_in[9];
    const float* u1     = (const float*)d_in[10];
    const float* bg1    = (const float*)d_in[11];
    const float* bu1    = (const float*)d_in[12];
    const float* zeta1  = (const float*)d_in[13];
    const float* nu1    = (const float*)d_in[14];
    const float* lambd1 = (const float*)d_in[15];
    const float* gamma1 = (const float*)d_in[16];
    (void)in_sizes; (void)n_in; (void)out_size;

    float* out = (float*)d_out;                    // out1: [B, S, H]
    float* hT0 = out + (size_t)DB * DS * DH;       // h_n[0]
    float* hT1 = hT0 + (size_t)DB * DH;            // h_n[1]

    void* p;
    cudaGetSymbolAddress(&p, g_wx0);
    float* wx0p = (float*)p;

    static int smem_set = 0;
    if (!smem_set) {
        cudaFuncSetAttribute(gemm_rows<DI>,
                             cudaFuncAttributeMaxDynamicSharedMemorySize, DI * DH * 4);
        smem_set = 1;
    }

    reset_kernel<<<2, 1024>>>();
    gemm_rows<DI><<<(DB * DS) / 256, 256, DI * DH * 4>>>(x, w0, wx0p);
    pipe_kernel<<<2 * DB, 192>>>(
        u0, u1, w1,
        bg0, bu0, zeta0, nu0, lambd0, gamma0,
        bg1, bu1, zeta1, nu1, lambd1, gamma1,
        out, hT0, hT1);
}